// round 7
// baseline (speedup 1.0000x reference)
#include <cuda_runtime.h>
#include <cuda_bf16.h>

// Problem constants: N=100000, E=3200000, F_in=128, H=25, C=40
#define MAXN 100000
#define MAXE 3200000
#define FIN  128
#define H1   25
#define H1P  32        // padded pitch: 128B rows for h1p and ap
#define C2   40

// Scratch (__device__ globals; zero-init at module load)
__device__ float g_dinv[MAXN];
__device__ int   g_cnt [MAXN];
__device__ int   g_row [MAXN + 1];
__device__ int   g_cur [MAXN];
__device__ int   g_psum[128];
__device__ int   g_poff[128];
__device__ int2  g_edge[MAXE];         // build: {src, w_bits}; after agg1: {src, norm_bits}
__device__ float g_h1p [MAXN * H1P];   // x @ W1 (pad cols never written -> stay 0)
__device__ float g_ap  [MAXN * H1P];   // relu(agg1+self+b1), pad cols written 0
__device__ int   g_is64;

// ---------------------------------------------------------------------------
__global__ void detect_kernel(const int* __restrict__ ei) {
    int all0 = 1;
    for (int k = 0; k < 64; k++)
        if (ei[2 * k + 1] != 0) { all0 = 0; break; }
    g_is64 = all0;
}

__device__ __forceinline__ int ld_node(const int* __restrict__ ei32,
                                       long long pos, int is64) {
    return ei32[is64 ? (pos << 1) : pos];   // little-endian low word
}

// ---------------------------------------------------------------------------
__global__ void init_kernel(int N) {
    int i = blockIdx.x * blockDim.x + threadIdx.x;
    if (i < N) g_cnt[i] = 0;
}

// in-degree histogram (int only — no float atomics)
__global__ void cnt_kernel(const int* __restrict__ ei32, int E) {
    int e = blockIdx.x * blockDim.x + threadIdx.x;
    if (e >= E) return;
    int d = ld_node(ei32, (long long)E + e, g_is64);
    atomicAdd(&g_cnt[d], 1);
}

// ---------------------------------------------------------------------------
// 3-phase scan of g_cnt -> g_row (exclusive), g_cur copy, g_row[N]=E.
__global__ void scan_local(int N) {
    __shared__ int sh[1024];
    int i = blockIdx.x * 1024 + threadIdx.x;
    int v = (i < N) ? g_cnt[i] : 0;
    sh[threadIdx.x] = v;
    __syncthreads();
    int acc = v;
    for (int off = 1; off < 1024; off <<= 1) {
        int p = (threadIdx.x >= off) ? sh[threadIdx.x - off] : 0;
        __syncthreads();
        acc += p;
        sh[threadIdx.x] = acc;
        __syncthreads();
    }
    if (i < N) g_row[i] = acc - v;
    if (threadIdx.x == 1023) g_psum[blockIdx.x] = acc;
}

__global__ void scan_tops(int NB, int N, int E) {
    __shared__ int sh[128];
    int t = threadIdx.x;
    int v = (t < NB) ? g_psum[t] : 0;
    sh[t] = v;
    __syncthreads();
    int acc = v;
    for (int off = 1; off < 128; off <<= 1) {
        int p = (t >= off) ? sh[t - off] : 0;
        __syncthreads();
        acc += p;
        sh[t] = acc;
        __syncthreads();
    }
    if (t < NB) g_poff[t] = acc - v;
    if (t == 0) g_row[N] = E;
}

__global__ void scan_add(int N) {
    int i = blockIdx.x * blockDim.x + threadIdx.x;
    if (i >= N) return;
    int r = g_row[i] + g_poff[i >> 10];
    g_row[i] = r;
    g_cur[i] = r;
}

// Bucket-scatter edges: store raw (src, w). No dinv reads here.
__global__ void build_kernel(const int* __restrict__ ei32,
                             const float* __restrict__ w, int E) {
    int e = blockIdx.x * blockDim.x + threadIdx.x;
    if (e >= E) return;
    int is64 = g_is64;
    int s = ld_node(ei32, e, is64);
    int d = ld_node(ei32, (long long)E + e, is64);
    int pos = atomicAdd(&g_cur[d], 1);
    g_edge[pos] = make_int2(s, __float_as_int(w[e]));
}

// Streaming degree: warp per node, sum w over CSR row (coalesced) -> dinv.
#define WPBD 8
__global__ void deg_kernel(int N) {
    int warp = threadIdx.x >> 5;
    int lane = threadIdx.x & 31;
    int i = blockIdx.x * WPBD + warp;
    if (i >= N) return;
    int j0 = g_row[i], j1 = g_row[i + 1];
    float s = 0.0f;
    for (int j = j0 + lane; j < j1; j += 32)
        s += __int_as_float(__ldg(&g_edge[j]).y);
    #pragma unroll
    for (int off = 16; off > 0; off >>= 1)
        s += __shfl_xor_sync(0xffffffffu, s, off);
    if (lane == 0) g_dinv[i] = rsqrtf(s + 1.0f);   // +1 = self-loop weight
}

// ---------------------------------------------------------------------------
// GEMM1: h1p[N,32] = x[N,128] @ W1[128,25]. 4 rows x 5 cols per thread.
#define G1_TB   320
#define G1_RPB  256
__global__ void gemm1_kernel(const float* __restrict__ x,
                             const float* __restrict__ W1, int N) {
    __shared__ float ws[FIN * H1];
    for (int i = threadIdx.x; i < FIN * H1; i += G1_TB) ws[i] = W1[i];
    __syncthreads();

    int rowGroup = threadIdx.x / 5;
    int colGroup = threadIdx.x % 5;
    int r0 = blockIdx.x * G1_RPB + rowGroup * 4;
    int c0 = colGroup * 5;

    float acc[4][5];
    #pragma unroll
    for (int a = 0; a < 4; a++)
        #pragma unroll
        for (int b = 0; b < 5; b++) acc[a][b] = 0.0f;

    #pragma unroll 4
    for (int kb = 0; kb < FIN / 4; kb++) {
        float xr[4][4];
        #pragma unroll
        for (int a = 0; a < 4; a++) {
            int r = r0 + a;
            float4 v = (r < N) ? __ldg((const float4*)(x + (size_t)r * FIN) + kb)
                               : make_float4(0.f, 0.f, 0.f, 0.f);
            xr[a][0] = v.x; xr[a][1] = v.y; xr[a][2] = v.z; xr[a][3] = v.w;
        }
        #pragma unroll
        for (int t = 0; t < 4; t++) {
            int k = kb * 4 + t;
            float wv[5];
            #pragma unroll
            for (int b = 0; b < 5; b++) wv[b] = ws[k * H1 + c0 + b];
            #pragma unroll
            for (int a = 0; a < 4; a++)
                #pragma unroll
                for (int b = 0; b < 5; b++) acc[a][b] += xr[a][t] * wv[b];
        }
    }

    #pragma unroll
    for (int a = 0; a < 4; a++) {
        int r = r0 + a;
        if (r >= N) break;
        #pragma unroll
        for (int b = 0; b < 5; b++)
            g_h1p[(size_t)r * H1P + c0 + b] = acc[a][b];
    }
}

// ---------------------------------------------------------------------------
// Layer-1: aggregate h1p with on-the-fly norm; fold norm back into g_edge
// for agg2; + self + b1 + ReLU -> ap (pad lanes written 0).
#define WPB1 8
__global__ void agg1_kernel(const float* __restrict__ b1, int N) {
    __shared__ float b1s[H1];
    if (threadIdx.x < H1) b1s[threadIdx.x] = b1[threadIdx.x];
    __syncthreads();

    int warp = threadIdx.x >> 5;
    int lane = threadIdx.x & 31;
    int i = blockIdx.x * WPB1 + warp;
    if (i >= N) return;

    float dvI = g_dinv[i];
    float acc = dvI * dvI * __ldg(&g_h1p[(size_t)i * H1P + lane]);

    int j0 = g_row[i], j1 = g_row[i + 1];
    for (int j = j0; j < j1; j++) {
        int2  e  = g_edge[j];                   // plain load (we write it below)
        float nm = __ldg(&g_dinv[e.x]) * __int_as_float(e.y) * dvI;
        acc += nm * __ldg(&g_h1p[(size_t)e.x * H1P + lane]);
        if (lane == 0) g_edge[j] = make_int2(e.x, __float_as_int(nm));
    }

    float a = 0.0f;
    if (lane < H1) {
        a = acc + b1s[lane];
        a = a > 0.0f ? a : 0.0f;
    }
    g_ap[(size_t)i * H1P + lane] = a;           // full 128B row store
}

// ---------------------------------------------------------------------------
// Layer-2: aggregate ap (25-dim!) with folded norms, then GEMM2 + b2 +
// log-softmax. (Linearity: segsum(nm * a@W2) == segsum(nm*a) @ W2.)
#define WPB2 8
__global__ void agg2_kernel(float* __restrict__ out,
                            const float* __restrict__ W2,
                            const float* __restrict__ b2, int N) {
    __shared__ float w2s[H1 * C2];
    __shared__ float b2s[C2];
    __shared__ float sa[WPB2][H1];
    for (int k = threadIdx.x; k < H1 * C2; k += WPB2 * 32) w2s[k] = W2[k];
    if (threadIdx.x < C2) b2s[threadIdx.x] = b2[threadIdx.x];
    __syncthreads();

    int warp = threadIdx.x >> 5;
    int lane = threadIdx.x & 31;
    int i = blockIdx.x * WPB2 + warp;
    if (i >= N) return;

    float dvI = g_dinv[i];
    float acc = dvI * dvI * __ldg(&g_ap[(size_t)i * H1P + lane]);

    int j0 = g_row[i], j1 = g_row[i + 1];
    for (int j = j0; j < j1; j++) {
        int2 e = __ldg(&g_edge[j]);             // {src, norm_bits}
        acc += __int_as_float(e.y) * __ldg(&g_ap[(size_t)e.x * H1P + lane]);
    }

    if (lane < H1) sa[warp][lane] = acc;
    __syncwarp();

    // GEMM2 row + bias
    const float* a = sa[warp];
    bool has1 = (lane < C2 - 32);
    float o0 = b2s[lane];
    float o1 = has1 ? b2s[lane + 32] : 0.0f;
    #pragma unroll
    for (int k = 0; k < H1; k++) {
        float av = a[k];
        o0 += av * w2s[k * C2 + lane];
        if (has1) o1 += av * w2s[k * C2 + lane + 32];
    }

    // log-softmax over 40 values spread across the warp
    float m = fmaxf(o0, has1 ? o1 : -3.4e38f);
    #pragma unroll
    for (int off = 16; off > 0; off >>= 1)
        m = fmaxf(m, __shfl_xor_sync(0xffffffffu, m, off));
    float s = __expf(o0 - m) + (has1 ? __expf(o1 - m) : 0.0f);
    #pragma unroll
    for (int off = 16; off > 0; off >>= 1)
        s += __shfl_xor_sync(0xffffffffu, s, off);
    float lse = m + logf(s);

    out[(size_t)i * C2 + lane] = o0 - lse;
    if (has1) out[(size_t)i * C2 + 32 + lane] = o1 - lse;
}

// ---------------------------------------------------------------------------
extern "C" void kernel_launch(void* const* d_in, const int* in_sizes, int n_in,
                              void* d_out, int out_size) {
    const float* x    = (const float*)d_in[0];
    const int*   ei32 = (const int*)d_in[1];
    const float* w    = (const float*)d_in[2];
    const float* W1   = (const float*)d_in[3];
    const float* b1   = (const float*)d_in[4];
    const float* W2   = (const float*)d_in[5];
    const float* b2   = (const float*)d_in[6];
    float* out = (float*)d_out;

    int E = in_sizes[2];
    int N = in_sizes[0] / FIN;

    const int TB = 256;
    int gridE = (E + TB - 1) / TB;
    int gridN = (N + TB - 1) / TB;
    int NB    = (N + 1023) / 1024;

    detect_kernel<<<1, 1>>>(ei32);
    init_kernel<<<gridN, TB>>>(N);
    gemm1_kernel<<<(N + G1_RPB - 1) / G1_RPB, G1_TB>>>(x, W1, N);
    cnt_kernel<<<gridE, TB>>>(ei32, E);
    scan_local<<<NB, 1024>>>(N);
    scan_tops<<<1, 128>>>(NB, N, E);
    scan_add<<<gridN, TB>>>(N);
    build_kernel<<<gridE, TB>>>(ei32, w, E);
    deg_kernel<<<(N + WPBD - 1) / WPBD, WPBD * 32>>>(N);
    agg1_kernel<<<(N + WPB1 - 1) / WPB1, WPB1 * 32>>>(b1, N);
    agg2_kernel<<<(N + WPB2 - 1) / WPB2, WPB2 * 32>>>(out, W2, b2, N);
}

// round 8
// speedup vs baseline: 1.1431x; 1.1431x over previous
#include <cuda_runtime.h>
#include <cuda_bf16.h>

// Problem constants: N=100000, E=3200000, F_in=128, H=25, C=40
#define MAXN 100000
#define MAXE 3200000
#define FIN  128
#define H1   25
#define H1P  32        // padded pitch: 128B rows (h1p, ap)
#define C2   40

// Scratch (__device__ globals — allocation-free rule; zero-init at load)
__device__ float g_deg [MAXN];
__device__ float g_dinv[MAXN];
__device__ int   g_cnt [MAXN];
__device__ int   g_row [MAXN + 1];
__device__ int   g_cur [MAXN];
__device__ int   g_psum[128];
__device__ int   g_poff[128];
__device__ int2  g_edge[MAXE];         // {src, float_bits(norm)} — norm folded at build
__device__ float g_h1p [MAXN * H1P];   // x @ W1, padded (pad cols stay 0)
__device__ float g_ap  [MAXN * H1P];   // relu(agg1 + self + b1), pad cols written 0
__device__ int   g_is64;

// ---------------------------------------------------------------------------
__global__ void detect_kernel(const int* __restrict__ ei) {
    int all0 = 1;
    for (int k = 0; k < 64; k++)
        if (ei[2 * k + 1] != 0) { all0 = 0; break; }
    g_is64 = all0;
}

__device__ __forceinline__ int ld_node(const int* __restrict__ ei32,
                                       long long pos, int is64) {
    return ei32[is64 ? (pos << 1) : pos];   // little-endian low word
}

// ---------------------------------------------------------------------------
__global__ void init_kernel(int N) {
    int i = blockIdx.x * blockDim.x + threadIdx.x;
    if (i < N) { g_deg[i] = 1.0f; g_cnt[i] = 0; }
}

__global__ void degree_kernel(const int* __restrict__ ei32,
                              const float* __restrict__ w, int E) {
    int e = blockIdx.x * blockDim.x + threadIdx.x;
    if (e >= E) return;
    int is64 = g_is64;
    int d = ld_node(ei32, (long long)E + e, is64);
    atomicAdd(&g_deg[d], w[e]);
    atomicAdd(&g_cnt[d], 1);
}

__global__ void dinv_kernel(int N) {
    int i = blockIdx.x * blockDim.x + threadIdx.x;
    if (i >= N) return;
    float d = g_deg[i];
    g_dinv[i] = (d > 0.0f) ? rsqrtf(d) : 0.0f;
}

// ---------------------------------------------------------------------------
// 3-phase scan of g_cnt -> g_row (exclusive), g_cur copy, g_row[N]=E.
__global__ void scan_local(int N) {
    __shared__ int sh[1024];
    int i = blockIdx.x * 1024 + threadIdx.x;
    int v = (i < N) ? g_cnt[i] : 0;
    sh[threadIdx.x] = v;
    __syncthreads();
    int acc = v;
    for (int off = 1; off < 1024; off <<= 1) {
        int p = (threadIdx.x >= off) ? sh[threadIdx.x - off] : 0;
        __syncthreads();
        acc += p;
        sh[threadIdx.x] = acc;
        __syncthreads();
    }
    if (i < N) g_row[i] = acc - v;
    if (threadIdx.x == 1023) g_psum[blockIdx.x] = acc;
}

__global__ void scan_tops(int NB, int N, int E) {
    __shared__ int sh[128];
    int t = threadIdx.x;
    int v = (t < NB) ? g_psum[t] : 0;
    sh[t] = v;
    __syncthreads();
    int acc = v;
    for (int off = 1; off < 128; off <<= 1) {
        int p = (t >= off) ? sh[t - off] : 0;
        __syncthreads();
        acc += p;
        sh[t] = acc;
        __syncthreads();
    }
    if (t < NB) g_poff[t] = acc - v;
    if (t == 0) g_row[N] = E;
}

__global__ void scan_add(int N) {
    int i = blockIdx.x * blockDim.x + threadIdx.x;
    if (i >= N) return;
    int r = g_row[i] + g_poff[i >> 10];
    g_row[i] = r;
    g_cur[i] = r;
}

// Bucket-scatter edges into CSR slots; norm folded here (as in R4).
__global__ void build_kernel(const int* __restrict__ ei32,
                             const float* __restrict__ w, int E) {
    int e = blockIdx.x * blockDim.x + threadIdx.x;
    if (e >= E) return;
    int is64 = g_is64;
    int s = ld_node(ei32, e, is64);
    int d = ld_node(ei32, (long long)E + e, is64);
    float nm = g_dinv[s] * w[e] * g_dinv[d];
    int pos = atomicAdd(&g_cur[d], 1);
    g_edge[pos] = make_int2(s, __float_as_int(nm));
}

// ---------------------------------------------------------------------------
// GEMM1: h1p[N,32] = x[N,128] @ W1[128,25]. 4 rows x 5 cols per thread.
#define G1_TB   320
#define G1_RPB  256
__global__ void gemm1_kernel(const float* __restrict__ x,
                             const float* __restrict__ W1, int N) {
    __shared__ float ws[FIN * H1];
    for (int i = threadIdx.x; i < FIN * H1; i += G1_TB) ws[i] = W1[i];
    __syncthreads();

    int rowGroup = threadIdx.x / 5;
    int colGroup = threadIdx.x % 5;
    int r0 = blockIdx.x * G1_RPB + rowGroup * 4;
    int c0 = colGroup * 5;

    float acc[4][5];
    #pragma unroll
    for (int a = 0; a < 4; a++)
        #pragma unroll
        for (int b = 0; b < 5; b++) acc[a][b] = 0.0f;

    #pragma unroll 4
    for (int kb = 0; kb < FIN / 4; kb++) {
        float xr[4][4];
        #pragma unroll
        for (int a = 0; a < 4; a++) {
            int r = r0 + a;
            float4 v = (r < N) ? __ldg((const float4*)(x + (size_t)r * FIN) + kb)
                               : make_float4(0.f, 0.f, 0.f, 0.f);
            xr[a][0] = v.x; xr[a][1] = v.y; xr[a][2] = v.z; xr[a][3] = v.w;
        }
        #pragma unroll
        for (int t = 0; t < 4; t++) {
            int k = kb * 4 + t;
            float wv[5];
            #pragma unroll
            for (int b = 0; b < 5; b++) wv[b] = ws[k * H1 + c0 + b];
            #pragma unroll
            for (int a = 0; a < 4; a++)
                #pragma unroll
                for (int b = 0; b < 5; b++) acc[a][b] += xr[a][t] * wv[b];
        }
    }

    #pragma unroll
    for (int a = 0; a < 4; a++) {
        int r = r0 + a;
        if (r >= N) break;
        #pragma unroll
        for (int b = 0; b < 5; b++)
            g_h1p[(size_t)r * H1P + c0 + b] = acc[a][b];
    }
}

// ---------------------------------------------------------------------------
// Layer-1: CSR aggregate (rolled loop, norms precomputed) + self + b1 + ReLU.
// Stores 128B row ap (pad lanes = 0). No GEMM2 here (moved to agg2 epilogue).
#define WPB1 8
__global__ void agg1_kernel(const float* __restrict__ b1, int N) {
    __shared__ float b1s[H1];
    if (threadIdx.x < H1) b1s[threadIdx.x] = b1[threadIdx.x];
    __syncthreads();

    int warp = threadIdx.x >> 5;
    int lane = threadIdx.x & 31;
    int i = blockIdx.x * WPB1 + warp;
    if (i >= N) return;

    float dv = g_dinv[i];
    float acc = dv * dv * __ldg(&g_h1p[(size_t)i * H1P + lane]);

    int j0 = g_row[i], j1 = g_row[i + 1];
    for (int j = j0; j < j1; j++) {
        int2 pr = __ldg(&g_edge[j]);                         // broadcast 8B
        acc += __int_as_float(pr.y) * __ldg(&g_h1p[(size_t)pr.x * H1P + lane]);
    }

    float a = 0.0f;
    if (lane < H1) {
        a = acc + b1s[lane];
        a = a > 0.0f ? a : 0.0f;
    }
    g_ap[(size_t)i * H1P + lane] = a;                        // full 128B store
}

// ---------------------------------------------------------------------------
// Layer-2: aggregate 25-dim ap (128B rows) with folded norms, then
// GEMM2 + b2 + log-softmax per node.  Linearity: segsum(nm*a)@W2.
#define WPB2 8
__global__ void agg2_kernel(float* __restrict__ out,
                            const float* __restrict__ W2,
                            const float* __restrict__ b2, int N) {
    __shared__ float w2s[H1 * C2];
    __shared__ float b2s[C2];
    __shared__ float sa[WPB2][H1];
    for (int k = threadIdx.x; k < H1 * C2; k += WPB2 * 32) w2s[k] = W2[k];
    if (threadIdx.x < C2) b2s[threadIdx.x] = b2[threadIdx.x];
    __syncthreads();

    int warp = threadIdx.x >> 5;
    int lane = threadIdx.x & 31;
    int i = blockIdx.x * WPB2 + warp;
    if (i >= N) return;

    float dv = g_dinv[i];
    float acc = dv * dv * __ldg(&g_ap[(size_t)i * H1P + lane]);

    int j0 = g_row[i], j1 = g_row[i + 1];
    for (int j = j0; j < j1; j++) {
        int2 pr = __ldg(&g_edge[j]);                         // {src, norm_bits}
        acc += __int_as_float(pr.y) * __ldg(&g_ap[(size_t)pr.x * H1P + lane]);
    }

    if (lane < H1) sa[warp][lane] = acc;
    __syncwarp();

    const float* a = sa[warp];
    bool has1 = (lane < C2 - 32);
    float o0 = b2s[lane];
    float o1 = has1 ? b2s[lane + 32] : 0.0f;
    #pragma unroll
    for (int k = 0; k < H1; k++) {
        float av = a[k];
        o0 += av * w2s[k * C2 + lane];
        if (has1) o1 += av * w2s[k * C2 + lane + 32];
    }

    float m = fmaxf(o0, has1 ? o1 : -3.4e38f);
    #pragma unroll
    for (int off = 16; off > 0; off >>= 1)
        m = fmaxf(m, __shfl_xor_sync(0xffffffffu, m, off));
    float s = __expf(o0 - m) + (has1 ? __expf(o1 - m) : 0.0f);
    #pragma unroll
    for (int off = 16; off > 0; off >>= 1)
        s += __shfl_xor_sync(0xffffffffu, s, off);
    float lse = m + logf(s);

    out[(size_t)i * C2 + lane] = o0 - lse;
    if (has1) out[(size_t)i * C2 + 32 + lane] = o1 - lse;
}

// ---------------------------------------------------------------------------
extern "C" void kernel_launch(void* const* d_in, const int* in_sizes, int n_in,
                              void* d_out, int out_size) {
    const float* x    = (const float*)d_in[0];
    const int*   ei32 = (const int*)d_in[1];
    const float* w    = (const float*)d_in[2];
    const float* W1   = (const float*)d_in[3];
    const float* b1   = (const float*)d_in[4];
    const float* W2   = (const float*)d_in[5];
    const float* b2   = (const float*)d_in[6];
    float* out = (float*)d_out;

    int E = in_sizes[2];
    int N = in_sizes[0] / FIN;

    const int TB = 256;
    int gridE = (E + TB - 1) / TB;
    int gridN = (N + TB - 1) / TB;
    int NB    = (N + 1023) / 1024;

    detect_kernel<<<1, 1>>>(ei32);
    init_kernel<<<gridN, TB>>>(N);
    degree_kernel<<<gridE, TB>>>(ei32, w, E);
    dinv_kernel<<<gridN, TB>>>(N);
    scan_local<<<NB, 1024>>>(N);
    scan_tops<<<1, 128>>>(NB, N, E);
    scan_add<<<gridN, TB>>>(N);
    build_kernel<<<gridE, TB>>>(ei32, w, E);
    gemm1_kernel<<<(N + G1_RPB - 1) / G1_RPB, G1_TB>>>(x, W1, N);
    agg1_kernel<<<(N + WPB1 - 1) / WPB1, WPB1 * 32>>>(b1, N);
    agg2_kernel<<<(N + WPB2 - 1) / WPB2, WPB2 * 32>>>(out, W2, b2, N);
}